// round 1
// baseline (speedup 1.0000x reference)
#include <cuda_runtime.h>

// SGD_Hankel: tensor-train chain, N=65536 samples, L=128 steps, D=4, R=8, O=2.
// merged[8] <- merged @ M_t(x),  M_t[k,l] = sum_j core_t[k,j,l] * x[t,j]
// Exploits: (a) cores_mid[:, :, 3, :] == I  =>  j=3 term is x3*merged exactly.
//           (b) cores warp-uniform -> smem broadcast LDS.
//           (c) fp32x2 packed FMA over output-pairs (l0,l1) for 2x fp32 rate.

#define DV 4
#define RV 8
#define LV 128
#define NSTEP 126          // L-2 middle cores

typedef unsigned long long u64;

__device__ __forceinline__ u64 fpack(float a, float b) {
    u64 r; asm("mov.b64 %0, {%1,%2};" : "=l"(r) : "f"(a), "f"(b)); return r;
}
__device__ __forceinline__ void funpack(u64 v, float& a, float& b) {
    asm("mov.b64 {%0,%1}, %2;" : "=f"(a), "=f"(b) : "l"(v));
}
__device__ __forceinline__ u64 f2mul(u64 a, u64 b) {
    u64 d; asm("mul.rn.f32x2 %0, %1, %2;" : "=l"(d) : "l"(a), "l"(b)); return d;
}
__device__ __forceinline__ u64 f2fma(u64 a, u64 b, u64 c) {
    u64 d; asm("fma.rn.f32x2 %0, %1, %2, %3;" : "=l"(d) : "l"(a), "l"(b), "l"(c)); return d;
}

// smem: mid cores rearranged [s][j<3][k][l] + core_first[4][8] + core_last[8][4][2]
#define SMID_FLOATS (NSTEP * 3 * RV * RV)         // 24192
#define SMEM_FLOATS (SMID_FLOATS + DV*RV + RV*DV*2)
#define SMEM_BYTES  (SMEM_FLOATS * 4)             // 97152 B

extern "C" __global__ void __launch_bounds__(256, 2)
tt_chain_kernel(const float* __restrict__ x,
                const float* __restrict__ core_first,
                const float* __restrict__ cores_mid,
                const float* __restrict__ core_last,
                float* __restrict__ out,
                int n_total)
{
    extern __shared__ float sm[];
    float* smid   = sm;                       // [s][j][k][l], j in 0..2
    float* sfirst = sm + SMID_FLOATS;         // 32 floats [j][k]
    float* slast  = sfirst + DV * RV;         // 64 floats [k][j][l]

    const int tid = threadIdx.x;

    // Stage + rearrange mid cores: src [s][k][j][l] -> dst [s][j][k][l], j<3.
    // One float4 (half of l) per unit; 48 units per step.
    for (int i = tid; i < NSTEP * 48; i += blockDim.x) {
        int s = i / 48;
        int r = i - s * 48;
        int j = r >> 4;             // 0..2
        int k = (r >> 1) & 7;       // 0..7
        int h = r & 1;              // which float4 of the 8 l's
        float4 v = *(const float4*)(cores_mid + (((s * RV + k) * DV + j) * RV) + h * 4);
        *(float4*)(smid + (((s * 3 + j) * RV + k) * RV) + h * 4) = v;
    }
    if (tid < DV * RV)     sfirst[tid] = core_first[tid];
    if (tid < RV * DV * 2) slast[tid]  = core_last[tid];
    __syncthreads();

    const int n = blockIdx.x * blockDim.x + tid;
    if (n >= n_total) return;

    const float* xr = x + (size_t)n * (LV * DV);

    // ---- init: merged[k] = sum_j core_first[j][k] * x[n,0,j] ----
    float4 xv = *(const float4*)xr;
    u64 mp[4];   // merged as 4 packed pairs (m0,m1)(m2,m3)(m4,m5)(m6,m7)
    {
        float m[8];
        #pragma unroll
        for (int k = 0; k < 8; ++k)
            m[k] = sfirst[k] * xv.x + sfirst[8 + k] * xv.y
                 + sfirst[16 + k] * xv.z + sfirst[24 + k] * xv.w;
        #pragma unroll
        for (int p = 0; p < 4; ++p) mp[p] = fpack(m[2 * p], m[2 * p + 1]);
    }

    // ---- 126 middle steps ----
    const float* cp = smid;
    #pragma unroll 1
    for (int s = 0; s < NSTEP; ++s) {
        xv = *(const float4*)(xr + (s + 1) * DV);

        float ms[8];
        #pragma unroll
        for (int p = 0; p < 4; ++p) funpack(mp[p], ms[2 * p], ms[2 * p + 1]);
        u64 md[8];
        #pragma unroll
        for (int k = 0; k < 8; ++k) md[k] = fpack(ms[k], ms[k]);

        u64 Y[3][4];
        #pragma unroll
        for (int j = 0; j < 3; ++j) {
            const float* cj = cp + j * 64;
            #pragma unroll
            for (int k = 0; k < 8; ++k) {
                ulonglong2 cA = *(const ulonglong2*)(cj + k * 8);       // pairs (l0l1)(l2l3)
                ulonglong2 cB = *(const ulonglong2*)(cj + k * 8 + 4);   // pairs (l4l5)(l6l7)
                if (k == 0) {
                    Y[j][0] = f2mul(md[0], cA.x);
                    Y[j][1] = f2mul(md[0], cA.y);
                    Y[j][2] = f2mul(md[0], cB.x);
                    Y[j][3] = f2mul(md[0], cB.y);
                } else {
                    Y[j][0] = f2fma(md[k], cA.x, Y[j][0]);
                    Y[j][1] = f2fma(md[k], cA.y, Y[j][1]);
                    Y[j][2] = f2fma(md[k], cB.x, Y[j][2]);
                    Y[j][3] = f2fma(md[k], cB.y, Y[j][3]);
                }
            }
        }

        const u64 xd0 = fpack(xv.x, xv.x);
        const u64 xd1 = fpack(xv.y, xv.y);
        const u64 xd2 = fpack(xv.z, xv.z);
        const u64 xd3 = fpack(xv.w, xv.w);   // identity slice: j=3 term = x3 * merged
        #pragma unroll
        for (int p = 0; p < 4; ++p)
            mp[p] = f2fma(xd3, mp[p],
                    f2fma(xd2, Y[2][p],
                    f2fma(xd1, Y[1][p],
                    f2mul(xd0, Y[0][p]))));

        cp += 3 * 64;
    }

    // ---- final: out[l] = sum_j x_j * (sum_k m_k * core_last[k][j][l]),  O=2 ----
    xv = *(const float4*)(xr + (LV - 1) * DV);
    {
        float ms[8];
        #pragma unroll
        for (int p = 0; p < 4; ++p) funpack(mp[p], ms[2 * p], ms[2 * p + 1]);
        u64 md[8];
        #pragma unroll
        for (int k = 0; k < 8; ++k) md[k] = fpack(ms[k], ms[k]);

        u64 Yl[4];
        #pragma unroll
        for (int j = 0; j < 4; ++j) {
            u64 acc = f2mul(md[0], *(const u64*)(slast + j * 2));
            #pragma unroll
            for (int k = 1; k < 8; ++k)
                acc = f2fma(md[k], *(const u64*)(slast + (k * DV + j) * 2), acc);
            Yl[j] = acc;
        }
        u64 o = f2fma(fpack(xv.w, xv.w), Yl[3],
                f2fma(fpack(xv.z, xv.z), Yl[2],
                f2fma(fpack(xv.y, xv.y), Yl[1],
                f2mul(fpack(xv.x, xv.x), Yl[0]))));
        float o0, o1;
        funpack(o, o0, o1);
        float2 res; res.x = o0; res.y = o1;
        *(float2*)(out + 2 * (size_t)n) = res;
    }
}

extern "C" void kernel_launch(void* const* d_in, const int* in_sizes, int n_in,
                              void* d_out, int out_size)
{
    const float* x  = (const float*)d_in[0];
    const float* cf = (const float*)d_in[1];
    const float* cm = (const float*)d_in[2];
    const float* cl = (const float*)d_in[3];
    float* out = (float*)d_out;

    const int n_total = in_sizes[0] / (LV * DV);   // 65536

    // >48KB dynamic smem needs the opt-in attribute (host-side, capture-safe).
    cudaFuncSetAttribute(tt_chain_kernel,
                         cudaFuncAttributeMaxDynamicSharedMemorySize, SMEM_BYTES);

    const int threads = 256;
    const int blocks = (n_total + threads - 1) / threads;
    tt_chain_kernel<<<blocks, threads, SMEM_BYTES>>>(x, cf, cm, cl, out, n_total);
}

// round 2
// speedup vs baseline: 1.3807x; 1.3807x over previous
#include <cuda_runtime.h>

// SGD_Hankel TT-chain: N=65536, L=128, D=4, R=8, O=2.
// R1 was L1tex wavefront-bound (core LDS + 2KB-strided x LDG = 32 lines/instr).
// R2: S=2 samples/thread (amortize core LDS), warp-cooperative x staging via
// swizzled smem (full-line coalesced LDG), cores phased 63+63 steps in smem.

#define DV 4
#define RV 8
#define LV 128
#define NSTEP 126
#define HALF  63

typedef unsigned long long u64;

__device__ __forceinline__ u64 fpack(float a, float b) {
    u64 r; asm("mov.b64 %0, {%1,%2};" : "=l"(r) : "f"(a), "f"(b)); return r;
}
__device__ __forceinline__ u64 fdup(float a) {
    u64 r; asm("mov.b64 %0, {%1,%1};" : "=l"(r) : "f"(a)); return r;
}
__device__ __forceinline__ void funpack(u64 v, float& a, float& b) {
    asm("mov.b64 {%0,%1}, %2;" : "=f"(a), "=f"(b) : "l"(v));
}
__device__ __forceinline__ u64 f2mul(u64 a, u64 b) {
    u64 d; asm("mul.rn.f32x2 %0, %1, %2;" : "=l"(d) : "l"(a), "l"(b)); return d;
}
__device__ __forceinline__ u64 f2fma(u64 a, u64 b, u64 c) {
    u64 d; asm("fma.rn.f32x2 %0, %1, %2, %3;" : "=l"(d) : "l"(a), "l"(b), "l"(c)); return d;
}

// smem: phased cores [63][3][8][8] + xbuf 4 warps * 2048 words + first/last
#define SCORE_FLOATS (HALF * 3 * RV * RV)      // 12096
#define XBUF_FLOATS  (4 * 2048)                // 8192
#define SFL_OFF      (SCORE_FLOATS + XBUF_FLOATS)
#define SMEM_FLOATS  (SFL_OFF + 96)
#define SMEM_BYTES   (SMEM_FLOATS * 4)         // 81536

// Warp-level x chunk refill: stages 8 steps x 64 sample-rows (32 n0 + 32 n1)
// as full 128B-line coalesced LDG.128 + conflict-free swizzled STS.32.
__device__ __forceinline__ void refill_chunk(const float* __restrict__ x, float* xw,
                                             int base_w, int lane, int c, int n_total)
{
    const int s8 = lane & 7;
    const int g  = lane >> 3;
    const int sw = s8 << 2;
    #pragma unroll
    for (int it = 0; it < 16; ++it) {
        int r = g + it * 4;                           // local row 0..63
        int n = base_w + ((r & 32) ? (r - 32 + 128) : r);
        float4 v = make_float4(0.f, 0.f, 0.f, 0.f);
        if (n < n_total)
            v = *(const float4*)(x + (size_t)n * (LV * DV) + (c * 8 + s8) * 4);
        int ridx = (r ^ sw) + s8 * 64;
        xw[0 * 512 + ridx] = v.x;
        xw[1 * 512 + ridx] = v.y;
        xw[2 * 512 + ridx] = v.z;
        xw[3 * 512 + ridx] = v.w;
    }
}

extern "C" __global__ void __launch_bounds__(128, 2)
tt_chain_kernel(const float* __restrict__ x,
                const float* __restrict__ core_first,
                const float* __restrict__ cores_mid,
                const float* __restrict__ core_last,
                float* __restrict__ out,
                int n_total)
{
    extern __shared__ float sm[];
    float* score  = sm;                    // [63][3][8][8]
    float* xbuf   = sm + SCORE_FLOATS;
    float* sfirst = sm + SFL_OFF;          // 32 floats [j][k]
    float* slast  = sfirst + 32;           // 64 floats [k][j][l]

    const int tid  = threadIdx.x;
    const int lane = tid & 31;
    const int w    = tid >> 5;
    float* xw = xbuf + w * 2048;

    const int n0 = blockIdx.x * 256 + tid;
    const int n1 = n0 + 128;
    const int base_w = blockIdx.x * 256 + w * 32;

    if (tid < 32)            sfirst[tid] = core_first[tid];
    else if (tid < 96)       slast[tid - 32] = core_last[tid - 32];

    u64 mpA[4], mpB[4];

    #pragma unroll 1
    for (int phase = 0; phase < 2; ++phase) {
        __syncthreads();    // prior-phase consumers done before core overwrite
        // stage cores for this phase: [s][k][j][l] -> [s][j][k][l], j<3
        for (int u = tid; u < HALF * 48; u += 128) {
            int st = u / 48;
            int rr = u - st * 48;
            int j = rr >> 4, k = (rr >> 1) & 7, h = rr & 1;
            float4 v = *(const float4*)(cores_mid
                        + (((size_t)(phase * HALF + st) * RV + k) * DV + j) * RV + h * 4);
            *(float4*)(score + ((st * 3 + j) * RV + k) * RV + h * 4) = v;
        }
        __syncthreads();

        if (phase == 0) {
            // first x chunk + init merged from core_first with x[:,0]
            refill_chunk(x, xw, base_w, lane, 0, n_total);
            __syncwarp();
            float xa[4], xb[4];
            #pragma unroll
            for (int f = 0; f < 4; ++f) {
                xa[f] = xw[f * 512 + lane];
                xb[f] = xw[f * 512 + 32 + lane];
            }
            float mA[8], mB[8];
            #pragma unroll
            for (int k = 0; k < 8; ++k) {
                mA[k] = sfirst[k] * xa[0] + sfirst[8 + k] * xa[1]
                      + sfirst[16 + k] * xa[2] + sfirst[24 + k] * xa[3];
                mB[k] = sfirst[k] * xb[0] + sfirst[8 + k] * xb[1]
                      + sfirst[16 + k] * xb[2] + sfirst[24 + k] * xb[3];
            }
            #pragma unroll
            for (int p = 0; p < 4; ++p) {
                mpA[p] = fpack(mA[2 * p], mA[2 * p + 1]);
                mpB[p] = fpack(mB[2 * p], mB[2 * p + 1]);
            }
        }

        const float* cp = score;
        #pragma unroll 1
        for (int sc = 0; sc < HALF; ++sc) {
            const int l = phase * HALF + sc + 1;       // x index consumed this step
            if ((l & 7) == 0) {
                __syncwarp();
                refill_chunk(x, xw, base_w, lane, l >> 3, n_total);
                __syncwarp();
            }
            const int s8 = l & 7;
            const int ia = (lane ^ (s8 << 2)) + s8 * 64;

            // x reads (issue early to hide LDS latency)
            float xa[4], xb[4];
            #pragma unroll
            for (int f = 0; f < 4; ++f) {
                xa[f] = xw[f * 512 + ia];
                xb[f] = xw[f * 512 + 32 + ia];
            }

            // duplicate merged scalars into packed lanes
            u64 mdA[8], mdB[8];
            #pragma unroll
            for (int p = 0; p < 4; ++p) {
                float a0, a1, b0, b1;
                funpack(mpA[p], a0, a1);
                funpack(mpB[p], b0, b1);
                mdA[2 * p] = fdup(a0); mdA[2 * p + 1] = fdup(a1);
                mdB[2 * p] = fdup(b0); mdB[2 * p + 1] = fdup(b1);
            }

            u64 Ya[3][4], Yb[3][4];
            #pragma unroll
            for (int j = 0; j < 3; ++j) {
                const float* cj = cp + j * 64;
                #pragma unroll
                for (int k = 0; k < 8; ++k) {
                    ulonglong2 cA = *(const ulonglong2*)(cj + k * 8);
                    ulonglong2 cB = *(const ulonglong2*)(cj + k * 8 + 4);
                    if (k == 0) {
                        Ya[j][0] = f2mul(mdA[0], cA.x); Ya[j][1] = f2mul(mdA[0], cA.y);
                        Ya[j][2] = f2mul(mdA[0], cB.x); Ya[j][3] = f2mul(mdA[0], cB.y);
                        Yb[j][0] = f2mul(mdB[0], cA.x); Yb[j][1] = f2mul(mdB[0], cA.y);
                        Yb[j][2] = f2mul(mdB[0], cB.x); Yb[j][3] = f2mul(mdB[0], cB.y);
                    } else {
                        Ya[j][0] = f2fma(mdA[k], cA.x, Ya[j][0]);
                        Ya[j][1] = f2fma(mdA[k], cA.y, Ya[j][1]);
                        Ya[j][2] = f2fma(mdA[k], cB.x, Ya[j][2]);
                        Ya[j][3] = f2fma(mdA[k], cB.y, Ya[j][3]);
                        Yb[j][0] = f2fma(mdB[k], cA.x, Yb[j][0]);
                        Yb[j][1] = f2fma(mdB[k], cA.y, Yb[j][1]);
                        Yb[j][2] = f2fma(mdB[k], cB.x, Yb[j][2]);
                        Yb[j][3] = f2fma(mdB[k], cB.y, Yb[j][3]);
                    }
                }
            }

            // identity slice: j=3 term is x3 * merged (exact)
            const u64 a0 = fdup(xa[0]), a1 = fdup(xa[1]), a2 = fdup(xa[2]), a3 = fdup(xa[3]);
            const u64 b0 = fdup(xb[0]), b1 = fdup(xb[1]), b2 = fdup(xb[2]), b3 = fdup(xb[3]);
            #pragma unroll
            for (int p = 0; p < 4; ++p) {
                mpA[p] = f2fma(a3, mpA[p],
                         f2fma(a2, Ya[2][p],
                         f2fma(a1, Ya[1][p],
                         f2mul(a0, Ya[0][p]))));
                mpB[p] = f2fma(b3, mpB[p],
                         f2fma(b2, Yb[2][p],
                         f2fma(b1, Yb[1][p],
                         f2mul(b0, Yb[0][p]))));
            }
            cp += 3 * 64;
        }
    }

    // ---- final contraction with core_last: out[l] = sum_j x_j (sum_k m_k C[k][j][l]) ----
    {
        const int l = LV - 1;                  // 127, chunk 15 already staged
        const int s8 = l & 7;
        const int ia = (lane ^ (s8 << 2)) + s8 * 64;
        float xa[4], xb[4];
        #pragma unroll
        for (int f = 0; f < 4; ++f) {
            xa[f] = xw[f * 512 + ia];
            xb[f] = xw[f * 512 + 32 + ia];
        }
        u64 mdA[8], mdB[8];
        #pragma unroll
        for (int p = 0; p < 4; ++p) {
            float a0, a1, b0, b1;
            funpack(mpA[p], a0, a1);
            funpack(mpB[p], b0, b1);
            mdA[2 * p] = fdup(a0); mdA[2 * p + 1] = fdup(a1);
            mdB[2 * p] = fdup(b0); mdB[2 * p + 1] = fdup(b1);
        }
        u64 YlA[4], YlB[4];
        #pragma unroll
        for (int j = 0; j < 4; ++j) {
            u64 accA = f2mul(mdA[0], *(const u64*)(slast + j * 2));
            u64 accB = f2mul(mdB[0], *(const u64*)(slast + j * 2));
            #pragma unroll
            for (int k = 1; k < 8; ++k) {
                u64 cv = *(const u64*)(slast + (k * DV + j) * 2);
                accA = f2fma(mdA[k], cv, accA);
                accB = f2fma(mdB[k], cv, accB);
            }
            YlA[j] = accA; YlB[j] = accB;
        }
        u64 oA = f2fma(fdup(xa[3]), YlA[3],
                 f2fma(fdup(xa[2]), YlA[2],
                 f2fma(fdup(xa[1]), YlA[1],
                 f2mul(fdup(xa[0]), YlA[0]))));
        u64 oB = f2fma(fdup(xb[3]), YlB[3],
                 f2fma(fdup(xb[2]), YlB[2],
                 f2fma(fdup(xb[1]), YlB[1],
                 f2mul(fdup(xb[0]), YlB[0]))));
        float r0, r1;
        if (n0 < n_total) {
            funpack(oA, r0, r1);
            float2 res; res.x = r0; res.y = r1;
            *(float2*)(out + 2 * (size_t)n0) = res;
        }
        if (n1 < n_total) {
            funpack(oB, r0, r1);
            float2 res; res.x = r0; res.y = r1;
            *(float2*)(out + 2 * (size_t)n1) = res;
        }
    }
}

extern "C" void kernel_launch(void* const* d_in, const int* in_sizes, int n_in,
                              void* d_out, int out_size)
{
    const float* x  = (const float*)d_in[0];
    const float* cf = (const float*)d_in[1];
    const float* cm = (const float*)d_in[2];
    const float* cl = (const float*)d_in[3];
    float* out = (float*)d_out;

    const int n_total = in_sizes[0] / (LV * DV);   // 65536

    cudaFuncSetAttribute(tt_chain_kernel,
                         cudaFuncAttributeMaxDynamicSharedMemorySize, SMEM_BYTES);

    const int threads = 128;
    const int blocks = (n_total + 255) / 256;      // 2 samples per thread
    tt_chain_kernel<<<blocks, threads, SMEM_BYTES>>>(x, cf, cm, cl, out, n_total);
}